// round 5
// baseline (speedup 1.0000x reference)
#include <cuda_runtime.h>
#include <cstdint>

#define E_DIM 256
#define D_DIM 128
#define MT    64           // tokens per CTA
#define KCH   16           // K chunk

// smem float-offset layout
//  GEMM phase: buf0 [0,7168), buf1 [7168,14336)
//    each buf: x-frag 1024 fl, then 3 * 2048 fl W-frag
//  attention phase (aliases GEMM bufs, which are dead):
//    q [0,8448), k [8448,16896), v [16896,25344)
#define BUF_FL  7168
#define QSTR    132
#define F_Q     0
#define F_K     8448
#define F_V     16896
#define F_PR    25344
#define F_BI    25856
#define SMEM_FLOATS 26240          // 104,960 B -> 2 CTAs/SM

__device__ float g_W[3 * E_DIM * E_DIM];   // fragment-major, see prep
__device__ float g_b[3 * E_DIM];

__device__ __forceinline__ float tf32r(float x) {
    float r; asm("cvt.rna.tf32.f32 %0, %1;" : "=f"(r) : "f"(x)); return r;
}

#define MMA_TF32(c, a, b0, b1) \
    asm volatile("mma.sync.aligned.m16n8k8.row.col.f32.tf32.tf32.f32 " \
        "{%0,%1,%2,%3}, {%4,%5,%6,%7}, {%8,%9}, {%0,%1,%2,%3};" \
        : "+f"((c)[0]), "+f"((c)[1]), "+f"((c)[2]), "+f"((c)[3]) \
        : "r"(a[0]), "r"(a[1]), "r"(a[2]), "r"(a[3]), "r"(b0), "r"(b1))

#define CP_ASYNC4(dst, src) \
    asm volatile("cp.async.ca.shared.global [%0], [%1], 4;" :: "r"(dst), "l"(src))
#define CP_ASYNC16(dst, src) \
    asm volatile("cp.async.ca.shared.global [%0], [%1], 16;" :: "r"(dst), "l"(src))
#define CP_COMMIT()  asm volatile("cp.async.commit_group;" ::: "memory")
#define CP_WAIT1()   asm volatile("cp.async.wait_group 1;" ::: "memory")
#define CP_WAIT0()   asm volatile("cp.async.wait_group 0;" ::: "memory")

// Fold P into Wq/Wk; write weights in per-thread MMA fragment order:
// idx = (((((p*2+head)*16+kc)*2+k8)*2+kh)*4+wn)*32+lane)*4 + j
// where thread `lane` of warp-col `wn` reads {b[j][kh]} = W[k][n] with
//   k = kc*16 + k8*8 + kh*4 + (lane&3),  n = wn*32 + j*8 + (lane>>2)  (n within head)
__global__ void prep_kernel(const float* __restrict__ Wq, const float* __restrict__ bq,
                            const float* __restrict__ Wk, const float* __restrict__ bk,
                            const float* __restrict__ Wv, const float* __restrict__ bv,
                            const float* __restrict__ P) {
    int e = blockIdx.x, j = threadIdx.x;        // e = k (input feat), j = out col
    int h = j >> 7, jm = j & 127;
    float aq = 0.f, ak = 0.f;
#pragma unroll 4
    for (int d = 0; d < D_DIM; ++d) {
        float p = P[d * D_DIM + jm];
        aq = fmaf(Wq[(h * D_DIM + d) * E_DIM + e], p, aq);
        ak = fmaf(Wk[(h * D_DIM + d) * E_DIM + e], p, ak);
    }
    int kc = e >> 4, kr = e & 15;
    int k8 = kr >> 3, kl = kr & 7, kh = kl >> 2;
    int lane = ((jm & 7) << 2) | (kl & 3);
    int j4 = (jm >> 3) & 3, wn = jm >> 5;
    size_t base = ((((((size_t)h * 16 + kc) * 2 + k8) * 2 + kh) * 4 + wn) * 32 + lane) * 4 + j4;
    g_W[0 * 65536 + base + 0] = tf32r(aq);           // p stride = 2*65536/… : p*2 folded below
    g_W[1 * 65536 + base]     = tf32r(ak);
    g_W[2 * 65536 + base]     = tf32r(Wv[j * E_DIM + e]);
    if (e == 0) {
        float bqe = 0.f, bke = 0.f;
        for (int d = 0; d < D_DIM; ++d) {
            float p = P[d * D_DIM + jm];
            bqe = fmaf(bq[h * D_DIM + d], p, bqe);
            bke = fmaf(bk[h * D_DIM + d], p, bke);
        }
        g_b[0 * E_DIM + j] = bqe;
        g_b[1 * E_DIM + j] = bke;
        g_b[2 * E_DIM + j] = bv[j];
    }
}

// CTA = 64 tokens x 1 head; single merged k-loop computes q,k,v together.
__global__ __launch_bounds__(256, 2)
void fused_kernel(const float* __restrict__ x, float* __restrict__ out) {
    extern __shared__ float sm[];
    const int tid  = threadIdx.x;
    const int w    = tid >> 5, lane = tid & 31;
    const int wm   = w >> 2, wn = w & 3;          // warp grid 2x4 over [64,128]
    const int tile = blockIdx.x >> 1, head = blockIdx.x & 1;

    uint32_t smb;
    asm("{\n\t.reg .u64 t;\n\tcvta.to.shared.u64 t, %1;\n\tcvt.u32.u64 %0, t;\n\t}"
        : "=r"(smb) : "l"(sm));

    const float* xg = x + (size_t)tile * MT * E_DIM;
    // W source for this head: chunk kc of p lives at g_W + p*65536 + (head*16+kc)*2048
    const float* wgh = g_W + (size_t)head * 32768;

    // stage bias
    for (int i = tid; i < 384; i += 256)
        sm[F_BI + i] = g_b[(i >> 7) * E_DIM + head * D_DIM + (i & 127)];

    // ---- issue chunk 0 ----
    auto issue = [&](int kc, uint32_t bufb) {
        // x: 1024 floats, scattered into A-fragment order
#pragma unroll
        for (int i = 0; i < 4; ++i) {
            int e = i * 256 + tid;                 // element in 64x16 chunk
            int m = e >> 4, kf = e & 15;
            int k8 = kf >> 3, kl = kf & 7;
            uint32_t dfl = (uint32_t)(((k8 * 4 + (m >> 4)) * 32 + (((m & 7) << 2) | (kl & 3))) * 4
                                      + ((m >> 3) & 1) + 2 * (kl >> 2));
            CP_ASYNC4(bufb + dfl * 4u, xg + m * E_DIM + kc * KCH + kf);
        }
        // W: 3 x 2048 floats, identity copy (already fragment-major)
#pragma unroll
        for (int i = 0; i < 6; ++i) {
            int t = i * 256 + tid;                 // float4 id, 0..1535
            int p = t >> 9, r = t & 511;
            CP_ASYNC16(bufb + (1024u + (uint32_t)p * 2048u + (uint32_t)r * 4u) * 4u,
                       wgh + (size_t)p * 65536 + kc * 2048 + r * 4);
        }
        CP_COMMIT();
    };

    issue(0, smb);
    __syncthreads();                               // bias visible

    // accumulators, bias-initialized
    float acc[3][2][4][4];
#pragma unroll
    for (int p = 0; p < 3; ++p)
#pragma unroll
        for (int mi = 0; mi < 2; ++mi)
#pragma unroll
            for (int ni = 0; ni < 4; ++ni) {
                int col = wn * 32 + ni * 8 + 2 * (lane & 3);
                float b0 = sm[F_BI + p * 128 + col], b1 = sm[F_BI + p * 128 + col + 1];
                acc[p][mi][ni][0] = b0; acc[p][mi][ni][1] = b1;
                acc[p][mi][ni][2] = b0; acc[p][mi][ni][3] = b1;
            }

    for (int c = 0; c < 16; ++c) {
        const uint32_t bufb = smb + (uint32_t)(c & 1) * (BUF_FL * 4u);
        if (c < 15) issue(c + 1, smb + (uint32_t)((c + 1) & 1) * (BUF_FL * 4u));
        if (c < 15) { CP_WAIT1(); } else { CP_WAIT0(); }
        __syncthreads();
        const float4* bf4 = (const float4*)(sm + (size_t)(c & 1) * BUF_FL);
#pragma unroll
        for (int k8 = 0; k8 < 2; ++k8) {
            uint32_t a0[4], a1[4];
            *(float4*)a0 = bf4[(k8 * 4 + wm * 2 + 0) * 32 + lane];
            *(float4*)a1 = bf4[(k8 * 4 + wm * 2 + 1) * 32 + lane];
#pragma unroll
            for (int p = 0; p < 3; ++p) {
                uint32_t b0[4], b1[4];
                *(float4*)b0 = bf4[256 + p * 512 + ((k8 * 2 + 0) * 4 + wn) * 32 + lane];
                *(float4*)b1 = bf4[256 + p * 512 + ((k8 * 2 + 1) * 4 + wn) * 32 + lane];
#pragma unroll
                for (int ni = 0; ni < 4; ++ni) {
                    MMA_TF32(acc[p][0][ni], a0, b0[ni], b1[ni]);
                    MMA_TF32(acc[p][1][ni], a1, b0[ni], b1[ni]);
                }
            }
        }
        __syncthreads();
    }

    // ---- stage q/k/v (GEMM buffers now dead) ----
#pragma unroll
    for (int p = 0; p < 3; ++p) {
        float* stg = sm + p * 8448;
#pragma unroll
        for (int mi = 0; mi < 2; ++mi) {
            int row = wm * 32 + mi * 16 + (lane >> 2);
#pragma unroll
            for (int ni = 0; ni < 4; ++ni) {
                int col = wn * 32 + ni * 8 + 2 * (lane & 3);
                stg[row * QSTR + col]           = acc[p][mi][ni][0];
                stg[row * QSTR + col + 1]       = acc[p][mi][ni][1];
                stg[(row + 8) * QSTR + col]     = acc[p][mi][ni][2];
                stg[(row + 8) * QSTR + col + 1] = acc[p][mi][ni][3];
            }
        }
    }
    __syncthreads();

    // ---- block-diagonal attention: warp w -> block w ----
    float* qs = sm + F_Q; float* ks = sm + F_K; float* vs = sm + F_V;
    const float scl = 0.08838834764831845f;   // 1/sqrt(128)
    {
        int blk = w;
        int i0 = lane >> 3, j0 = lane & 7;
        const float4* q0 = (const float4*)(qs + (8 * blk + i0) * QSTR);
        const float4* q1 = (const float4*)(qs + (8 * blk + i0 + 4) * QSTR);
        const float4* k0 = (const float4*)(ks + (8 * blk + j0) * QSTR);
        float s0 = 0.f, s1 = 0.f;
#pragma unroll
        for (int t = 0; t < 32; ++t) {
            float4 kk = k0[t];
            float4 aa = q0[t];
            s0 += aa.x * kk.x + aa.y * kk.y + aa.z * kk.z + aa.w * kk.w;
            float4 cc = q1[t];
            s1 += cc.x * kk.x + cc.y * kk.y + cc.z * kk.z + cc.w * kk.w;
        }
        s0 *= scl; s1 *= scl;
        float m0 = s0, m1 = s1;
#pragma unroll
        for (int off = 1; off < 8; off <<= 1) {
            m0 = fmaxf(m0, __shfl_xor_sync(0xffffffffu, m0, off));
            m1 = fmaxf(m1, __shfl_xor_sync(0xffffffffu, m1, off));
        }
        float e0 = __expf(s0 - m0), e1 = __expf(s1 - m1);
        float d0 = e0, d1 = e1;
#pragma unroll
        for (int off = 1; off < 8; off <<= 1) {
            d0 += __shfl_xor_sync(0xffffffffu, d0, off);
            d1 += __shfl_xor_sync(0xffffffffu, d1, off);
        }
        sm[F_PR + blk * 64 + lane]      = e0 / d0;
        sm[F_PR + blk * 64 + 32 + lane] = e1 / d1;
        __syncwarp();

        const float* prob = sm + F_PR + blk * 64;
        float4 o[8];
#pragma unroll
        for (int i = 0; i < 8; ++i) o[i] = make_float4(0.f, 0.f, 0.f, 0.f);
#pragma unroll
        for (int j = 0; j < 8; ++j) {
            float4 v4 = *(const float4*)(vs + (8 * blk + j) * QSTR + lane * 4);
#pragma unroll
            for (int i = 0; i < 8; ++i) {
                float a = prob[i * 8 + j];
                o[i].x = fmaf(a, v4.x, o[i].x);
                o[i].y = fmaf(a, v4.y, o[i].y);
                o[i].z = fmaf(a, v4.z, o[i].z);
                o[i].w = fmaf(a, v4.w, o[i].w);
            }
        }
#pragma unroll
        for (int i = 0; i < 8; ++i) {
            size_t token = (size_t)tile * MT + 8 * blk + i;
            *(float4*)(out + token * E_DIM + head * D_DIM + lane * 4) = o[i];
        }
    }
}

extern "C" void kernel_launch(void* const* d_in, const int* in_sizes, int n_in,
                              void* d_out, int out_size) {
    const float* x  = (const float*)d_in[0];
    const float* Wq = (const float*)d_in[1];
    const float* bq = (const float*)d_in[2];
    const float* Wk = (const float*)d_in[3];
    const float* bk = (const float*)d_in[4];
    const float* Wv = (const float*)d_in[5];
    const float* bv = (const float*)d_in[6];
    const float* P  = (const float*)d_in[7];
    float* out = (float*)d_out;

    const int tokens = in_sizes[0] / E_DIM;      // B*N
    const int tiles  = tokens / MT;              // 1024
    const size_t smem = (size_t)SMEM_FLOATS * sizeof(float);   // 104,960 B

    cudaFuncSetAttribute(fused_kernel,
                         cudaFuncAttributeMaxDynamicSharedMemorySize, (int)smem);

    prep_kernel<<<E_DIM, E_DIM>>>(Wq, bq, Wk, bk, Wv, bv, P);
    fused_kernel<<<tiles * 2, 256, smem>>>(x, out);
}